// round 1
// baseline (speedup 1.0000x reference)
#include <cuda_runtime.h>
#include <cuda_bf16.h>
#include <cstdint>

// Problem constants
#define B 16
#define S 4096
#define H 768
#define T 2000

// Scratch: exclusive prefix sums of subtoken_lengths per batch.
// starts_excl[b][t] = sum of lengths[b][0..t-1]
__device__ int g_starts[B * T];

// ---------------------------------------------------------------------------
// Kernel 1: per-batch exclusive prefix sum over T lengths.
// One CTA per batch, 256 threads, 8 elements per thread (2048 >= 2000).
// ---------------------------------------------------------------------------
__global__ void scan_kernel(const int* __restrict__ lens) {
    const int b = blockIdx.x;
    const int tid = threadIdx.x;
    const int* L = lens + (size_t)b * T;

    __shared__ int ssum[256];

    int local[8];
    int s = 0;
#pragma unroll
    for (int i = 0; i < 8; i++) {
        int idx = tid * 8 + i;
        int v = (idx < T) ? L[idx] : 0;
        local[i] = s;   // exclusive within this thread's chunk
        s += v;
    }
    ssum[tid] = s;
    __syncthreads();

    // Hillis–Steele inclusive scan over 256 thread sums
#pragma unroll
    for (int off = 1; off < 256; off <<= 1) {
        int v = 0;
        if (tid >= off) v = ssum[tid - off];
        __syncthreads();
        if (tid >= off) ssum[tid] += v;
        __syncthreads();
    }

    int base = (tid > 0) ? ssum[tid - 1] : 0;
#pragma unroll
    for (int i = 0; i < 8; i++) {
        int idx = tid * 8 + i;
        if (idx < T) g_starts[(size_t)b * T + idx] = base + local[i];
    }
}

// ---------------------------------------------------------------------------
// Kernel 2: one warp per token. Sum len rows of hidden_states (len in {0,1,2}),
// scale by 1/len, write 768 floats. len==0 -> write zeros.
// Each lane handles 6 float4 (192 float4 per row, stride 32 lanes).
// ---------------------------------------------------------------------------
__global__ void __launch_bounds__(256) pool_kernel(
    const float* __restrict__ hs,      // [B, S, H]
    const int*   __restrict__ lens,    // [B, T]
    float*       __restrict__ out)     // [B, T, H]
{
    const int warp = (blockIdx.x * blockDim.x + threadIdx.x) >> 5;
    const int lane = threadIdx.x & 31;
    if (warp >= B * T) return;

    const int b = warp / T;
    const int len = lens[warp];
    const int start = g_starts[warp];   // exclusive prefix within batch b

    float4* dst = (float4*)(out + (size_t)warp * H);

    if (len == 0) {
        const float4 z = make_float4(0.f, 0.f, 0.f, 0.f);
#pragma unroll
        for (int k = 0; k < 6; k++) dst[lane + 32 * k] = z;
        return;
    }

    // First covered position is 1 + start (positions are 1-based in reference)
    const size_t row0 = (size_t)b * S + 1 + start;
    const float4* src0 = (const float4*)(hs + row0 * H);

    float4 acc[6];
#pragma unroll
    for (int k = 0; k < 6; k++) acc[k] = src0[lane + 32 * k];

    if (len == 2) {
        const float4* src1 = (const float4*)(hs + (row0 + 1) * H);
#pragma unroll
        for (int k = 0; k < 6; k++) {
            float4 v = src1[lane + 32 * k];
            acc[k].x += v.x; acc[k].y += v.y; acc[k].z += v.z; acc[k].w += v.w;
        }
        const float inv = 0.5f;
#pragma unroll
        for (int k = 0; k < 6; k++) {
            acc[k].x *= inv; acc[k].y *= inv; acc[k].z *= inv; acc[k].w *= inv;
        }
    }

#pragma unroll
    for (int k = 0; k < 6; k++) dst[lane + 32 * k] = acc[k];
}

// ---------------------------------------------------------------------------
extern "C" void kernel_launch(void* const* d_in, const int* in_sizes, int n_in,
                              void* d_out, int out_size)
{
    const float* hs   = (const float*)d_in[0];   // [B,S,H] fp32
    const int*   lens = (const int*)d_in[1];     // [B,T] int32
    float*       out  = (float*)d_out;           // [B,T,H] fp32

    (void)in_sizes; (void)n_in; (void)out_size;

    scan_kernel<<<B, 256>>>(lens);

    // one warp per token: B*T warps, 8 warps (256 threads) per block
    const int n_warps = B * T;
    const int blocks = (n_warps * 32 + 255) / 256;
    pool_kernel<<<blocks, 256>>>(hs, lens, out);
}

// round 2
// speedup vs baseline: 1.0009x; 1.0009x over previous
#include <cuda_runtime.h>
#include <cuda_bf16.h>
#include <cstdint>

// Problem constants
#define B 16
#define S 4096
#define H 768
#define T 2000

// Scratch: exclusive prefix sums of subtoken_lengths per batch.
// starts_excl[b][t] = sum of lengths[b][0..t-1]
__device__ int g_starts[B * T];

// ---------------------------------------------------------------------------
// Kernel 1: per-batch exclusive prefix sum over T lengths.
// One CTA per batch, 256 threads, 8 elements per thread (2048 >= 2000).
// ---------------------------------------------------------------------------
__global__ void scan_kernel(const int* __restrict__ lens) {
    const int b = blockIdx.x;
    const int tid = threadIdx.x;
    const int* L = lens + (size_t)b * T;

    __shared__ int ssum[256];

    int local[8];
    int s = 0;
#pragma unroll
    for (int i = 0; i < 8; i++) {
        int idx = tid * 8 + i;
        int v = (idx < T) ? L[idx] : 0;
        local[i] = s;   // exclusive within this thread's chunk
        s += v;
    }
    ssum[tid] = s;
    __syncthreads();

    // Hillis–Steele inclusive scan over 256 thread sums
#pragma unroll
    for (int off = 1; off < 256; off <<= 1) {
        int v = 0;
        if (tid >= off) v = ssum[tid - off];
        __syncthreads();
        if (tid >= off) ssum[tid] += v;
        __syncthreads();
    }

    int base = (tid > 0) ? ssum[tid - 1] : 0;
#pragma unroll
    for (int i = 0; i < 8; i++) {
        int idx = tid * 8 + i;
        if (idx < T) g_starts[(size_t)b * T + idx] = base + local[i];
    }
}

// ---------------------------------------------------------------------------
// Kernel 2: one warp per token. Sum len rows of hidden_states (len in {0,1,2}),
// scale by 1/len, write 768 floats. len==0 -> write zeros.
// Each lane handles 6 float4 (192 float4 per row, stride 32 lanes).
// ---------------------------------------------------------------------------
__global__ void __launch_bounds__(256) pool_kernel(
    const float* __restrict__ hs,      // [B, S, H]
    const int*   __restrict__ lens,    // [B, T]
    float*       __restrict__ out)     // [B, T, H]
{
    const int warp = (blockIdx.x * blockDim.x + threadIdx.x) >> 5;
    const int lane = threadIdx.x & 31;
    if (warp >= B * T) return;

    const int b = warp / T;
    const int len = lens[warp];
    const int start = g_starts[warp];   // exclusive prefix within batch b

    float4* dst = (float4*)(out + (size_t)warp * H);

    if (len == 0) {
        const float4 z = make_float4(0.f, 0.f, 0.f, 0.f);
#pragma unroll
        for (int k = 0; k < 6; k++) dst[lane + 32 * k] = z;
        return;
    }

    // First covered position is 1 + start (positions are 1-based in reference)
    const size_t row0 = (size_t)b * S + 1 + start;
    const float4* src0 = (const float4*)(hs + row0 * H);

    float4 acc[6];
#pragma unroll
    for (int k = 0; k < 6; k++) acc[k] = src0[lane + 32 * k];

    if (len == 2) {
        const float4* src1 = (const float4*)(hs + (row0 + 1) * H);
#pragma unroll
        for (int k = 0; k < 6; k++) {
            float4 v = src1[lane + 32 * k];
            acc[k].x += v.x; acc[k].y += v.y; acc[k].z += v.z; acc[k].w += v.w;
        }
        const float inv = 0.5f;
#pragma unroll
        for (int k = 0; k < 6; k++) {
            acc[k].x *= inv; acc[k].y *= inv; acc[k].z *= inv; acc[k].w *= inv;
        }
    }

#pragma unroll
    for (int k = 0; k < 6; k++) dst[lane + 32 * k] = acc[k];
}

// ---------------------------------------------------------------------------
extern "C" void kernel_launch(void* const* d_in, const int* in_sizes, int n_in,
                              void* d_out, int out_size)
{
    const float* hs   = (const float*)d_in[0];   // [B,S,H] fp32
    const int*   lens = (const int*)d_in[1];     // [B,T] int32
    float*       out  = (float*)d_out;           // [B,T,H] fp32

    (void)in_sizes; (void)n_in; (void)out_size;

    scan_kernel<<<B, 256>>>(lens);

    // one warp per token: B*T warps, 8 warps (256 threads) per block
    const int n_warps = B * T;
    const int blocks = (n_warps * 32 + 255) / 256;
    pool_kernel<<<blocks, 256>>>(hs, lens, out);
}